// round 2
// baseline (speedup 1.0000x reference)
#include <cuda_runtime.h>
#include <math.h>

// ---------------------------------------------------------------------------
// SpatialAttentionConv on GB300, fp32 + FFMA2 (fma.rn.f32x2) pipeline.
//
// Math rewrite:
//   QKV = x @ in_proj_w^T + in_proj_b              (N x 384)   [per-row, not per-gather]
//   per face i, neighbors j1..j8 (pad if j >= N):
//     per head h: s_k = <Q[i,h,:], K[jk,h,:]> / sqrt(32); masked softmax; o = sum attn*V
//   out = x @ Cw0^T + o @ W2^T + b2,  W2 = Cw1 @ Wo,  b2 = Cw1 @ bo + cb
// ---------------------------------------------------------------------------

#define MAXN 200064

static __device__ float g_qkv[(size_t)MAXN * 384];
static __device__ float g_o[(size_t)MAXN * 128];
static __device__ float g_w2[128 * 128];
static __device__ float g_cw0[128 * 128];
static __device__ float g_b2[128];
static __device__ int   g_is64;

// Detect whether face_neighborhood arrived as int64 or int32.
// If int64 (values < 2^31, nonneg), every odd int32 word is a zero high-word.
// If int32, odd words are real (mostly nonzero) indices.
__global__ void detect_kernel(const int* __restrict__ nbr32) {
    if (threadIdx.x == 0) {
        int any = 0;
        #pragma unroll 1
        for (int j = 1; j < 128; ++j) any |= nbr32[2 * j + 1];
        g_is64 = (any == 0) ? 1 : 0;
    }
}

// Fold out_proj + conv into a single 128x128 weight (W2) + bias (b2),
// and extract the strided conv tap 0 into a contiguous matrix (Cw0).
__global__ void prep_kernel(const float* __restrict__ conv_w,
                            const float* __restrict__ out_proj_w,
                            const float* __restrict__ out_proj_b,
                            const float* __restrict__ conv_b) {
    int n = blockIdx.x, i = threadIdx.x;   // n: out channel, i: in channel
    float s = 0.f;
    #pragma unroll 4
    for (int m = 0; m < 128; ++m)
        s += conv_w[(n * 128 + m) * 2 + 1] * out_proj_w[m * 128 + i];
    g_w2[n * 128 + i] = s;
    g_cw0[n * 128 + i] = conv_w[(n * 128 + i) * 2];
    if (i == 0) {
        float b = 0.f;
        for (int m = 0; m < 128; ++m)
            b += conv_w[(n * 128 + m) * 2 + 1] * out_proj_b[m];
        g_b2[n] = b + conv_b[n];
    }
}

// ---------------------------------------------------------------------------
// SGEMM: C[M x (gridDim.y*128)] = sum_pairs A_p @ B_p^T + bias.
// A: M x 128 row-major, B: rows x 128 row-major (each pair contributes K=128).
// BM=BN=128, BK=16, 256 threads, 8x8 micro-tile (split 4+4), FFMA2 inner loop.
// ---------------------------------------------------------------------------
template <int NPAIRS>
__global__ void __launch_bounds__(256)
sgemm_kernel(const float* __restrict__ A0, const float* __restrict__ B0,
             const float* __restrict__ A1, const float* __restrict__ B1,
             const float* __restrict__ bias, float* __restrict__ C,
             int M, int ldC) {
    constexpr int BM = 128, BN = 128, BK = 16;
    __shared__ float As[2][BK][BM];
    __shared__ float Bs[2][BK][BN];

    const int tid = threadIdx.x;
    const int tx = tid & 15;        // 16 col-groups
    const int ty = tid >> 4;        // 16 row-groups
    const int ar = tid >> 2;        // 0..63  (tile row for loads)
    const int ac = (tid & 3) << 2;  // 0,4,8,12 (k offset for loads)
    const int m0 = blockIdx.x * BM;
    const int n0 = blockIdx.y * BN;

    float4 rA[2], rB[2];
    auto gload = [&](int kt) {
        const float* A = (NPAIRS == 1 || kt < 8) ? A0 : A1;
        const float* B = (NPAIRS == 1 || kt < 8) ? B0 : B1;
        const int k0 = (kt & 7) * BK;
        #pragma unroll
        for (int rr = 0; rr < 2; ++rr) {
            int row = m0 + ar + rr * 64;
            rA[rr] = (row < M) ? *(const float4*)(A + (size_t)row * 128 + k0 + ac)
                               : make_float4(0.f, 0.f, 0.f, 0.f);
            rB[rr] = *(const float4*)(B + (size_t)(n0 + ar + rr * 64) * 128 + k0 + ac);
        }
    };
    auto sstore = [&](int buf) {
        #pragma unroll
        for (int rr = 0; rr < 2; ++rr) {
            As[buf][ac + 0][ar + rr * 64] = rA[rr].x;
            As[buf][ac + 1][ar + rr * 64] = rA[rr].y;
            As[buf][ac + 2][ar + rr * 64] = rA[rr].z;
            As[buf][ac + 3][ar + rr * 64] = rA[rr].w;
            Bs[buf][ac + 0][ar + rr * 64] = rB[rr].x;
            Bs[buf][ac + 1][ar + rr * 64] = rB[rr].y;
            Bs[buf][ac + 2][ar + rr * 64] = rB[rr].z;
            Bs[buf][ac + 3][ar + rr * 64] = rB[rr].w;
        }
    };

    // acc[i][j]: packed f32x2. rows: i<4 -> ty*4+i, else 64+ty*4+(i-4)
    //            col pairs: j<2 -> tx*4+2j, else 64+tx*4+2(j-2)
    unsigned long long acc[8][4];
    #pragma unroll
    for (int i = 0; i < 8; ++i)
        #pragma unroll
        for (int j = 0; j < 4; ++j) acc[i][j] = 0ull;

    gload(0);
    sstore(0);
    __syncthreads();

    const int nch = NPAIRS * 8;
    for (int kt = 0; kt < nch; ++kt) {
        const int buf = kt & 1;
        if (kt + 1 < nch) gload(kt + 1);
        #pragma unroll
        for (int k = 0; k < BK; ++k) {
            float a[8], b[8];
            *(float4*)&a[0] = *(const float4*)&As[buf][k][ty * 4];
            *(float4*)&a[4] = *(const float4*)&As[buf][k][64 + ty * 4];
            *(float4*)&b[0] = *(const float4*)&Bs[buf][k][tx * 4];
            *(float4*)&b[4] = *(const float4*)&Bs[buf][k][64 + tx * 4];
            unsigned long long bb[4];
            #pragma unroll
            for (int j = 0; j < 4; ++j) {
                unsigned int blo = __float_as_uint(b[2 * j]);
                unsigned int bhi = __float_as_uint(b[2 * j + 1]);
                asm("mov.b64 %0, {%1, %2};" : "=l"(bb[j]) : "r"(blo), "r"(bhi));
            }
            #pragma unroll
            for (int i = 0; i < 8; ++i) {
                unsigned int au = __float_as_uint(a[i]);
                unsigned long long aa;
                asm("mov.b64 %0, {%1, %1};" : "=l"(aa) : "r"(au));
                #pragma unroll
                for (int j = 0; j < 4; ++j)
                    asm("fma.rn.f32x2 %0, %1, %2, %0;"
                        : "+l"(acc[i][j]) : "l"(aa), "l"(bb[j]));
            }
        }
        if (kt + 1 < nch) sstore(buf ^ 1);
        __syncthreads();
    }

    // Epilogue: unpack, add bias, guarded vector stores.
    float bv[8];
    #pragma unroll
    for (int j = 0; j < 4; ++j) bv[j] = bias[n0 + tx * 4 + j];
    #pragma unroll
    for (int j = 0; j < 4; ++j) bv[4 + j] = bias[n0 + 64 + tx * 4 + j];

    #pragma unroll
    for (int i = 0; i < 8; ++i) {
        int row = m0 + ((i < 4) ? (ty * 4 + i) : (64 + ty * 4 + (i - 4)));
        if (row < M) {
            float r[8];
            #pragma unroll
            for (int j = 0; j < 4; ++j) {
                unsigned int lo, hi;
                asm("mov.b64 {%0, %1}, %2;" : "=r"(lo), "=r"(hi) : "l"(acc[i][j]));
                r[2 * j]     = __uint_as_float(lo) + bv[2 * j];
                r[2 * j + 1] = __uint_as_float(hi) + bv[2 * j + 1];
            }
            float* cp = C + (size_t)row * ldC + n0;
            *(float4*)(cp + tx * 4)      = make_float4(r[0], r[1], r[2], r[3]);
            *(float4*)(cp + 64 + tx * 4) = make_float4(r[4], r[5], r[6], r[7]);
        }
    }
}

// ---------------------------------------------------------------------------
// Attention: one warp per face. Lane l owns channels [4l, 4l+4); head = l/8.
// Gathers K,V rows (contiguous 1KB region per neighbor in the QKV buffer),
// masked softmax over 8 neighbors per head, writes o (N x 128).
// ---------------------------------------------------------------------------
__global__ void __launch_bounds__(256)
attn_kernel(const void* __restrict__ nbr, int N) {
    const int lane = threadIdx.x & 31;
    const int face = blockIdx.x * (blockDim.x >> 5) + (threadIdx.x >> 5);
    if (face >= N) return;

    const float* __restrict__ qkv = g_qkv;
    const float4 q = *(const float4*)&qkv[(size_t)face * 384 + lane * 4];

    int myj = 0;
    if (lane < 8) {
        if (g_is64) myj = (int)((const long long*)nbr)[(size_t)face * 9 + 1 + lane];
        else        myj = ((const int*)nbr)[(size_t)face * 9 + 1 + lane];
    }

    float  sc[8];
    float4 vv[8];
    const float scale = 0.17677669529663687f;  // 1/sqrt(32)

    #pragma unroll
    for (int kk = 0; kk < 8; ++kk) {
        int j = __shfl_sync(0xffffffffu, myj, kk);  // uniform across warp
        float s;
        float4 v;
        if (j < N) {
            const float* base = &qkv[(size_t)j * 384 + 128 + lane * 4];
            float4 kf = *(const float4*)base;          // K row slice
            v = *(const float4*)(base + 128);          // V row slice
            float p = q.x * kf.x + q.y * kf.y + q.z * kf.z + q.w * kf.w;
            p += __shfl_xor_sync(0xffffffffu, p, 1);
            p += __shfl_xor_sync(0xffffffffu, p, 2);
            p += __shfl_xor_sync(0xffffffffu, p, 4);   // 8-lane head reduce
            s = p * scale;
        } else {
            s = -INFINITY;
            v = make_float4(0.f, 0.f, 0.f, 0.f);
        }
        sc[kk] = s;
        vv[kk] = v;
    }

    float m = sc[0];
    #pragma unroll
    for (int kk = 1; kk < 8; ++kk) m = fmaxf(m, sc[kk]);
    float den = 0.f;
    #pragma unroll
    for (int kk = 0; kk < 8; ++kk) {
        float e = __expf(sc[kk] - m);
        sc[kk] = e;
        den += e;
    }
    const float inv = 1.0f / den;

    float4 acc = make_float4(0.f, 0.f, 0.f, 0.f);
    #pragma unroll
    for (int kk = 0; kk < 8; ++kk) {
        acc.x += sc[kk] * vv[kk].x;
        acc.y += sc[kk] * vv[kk].y;
        acc.z += sc[kk] * vv[kk].z;
        acc.w += sc[kk] * vv[kk].w;
    }
    acc.x *= inv; acc.y *= inv; acc.z *= inv; acc.w *= inv;

    *(float4*)&g_o[(size_t)face * 128 + lane * 4] = acc;
}

// ---------------------------------------------------------------------------
// Inputs (metadata order): 0 x, 1 face_neighborhood, 2 face_is_pad, 3 pad_size,
// 4 in_proj_w, 5 in_proj_b, 6 out_proj_w, 7 out_proj_b, 8 conv_w, 9 conv_b.
// ---------------------------------------------------------------------------
extern "C" void kernel_launch(void* const* d_in, const int* in_sizes, int n_in,
                              void* d_out, int out_size) {
    const float* x   = (const float*)d_in[0];
    const void*  nbr = d_in[1];
    const float* ipw = (const float*)d_in[4];
    const float* ipb = (const float*)d_in[5];
    const float* opw = (const float*)d_in[6];
    const float* opb = (const float*)d_in[7];
    const float* cw  = (const float*)d_in[8];
    const float* cb  = (const float*)d_in[9];
    const int N = in_sizes[0] / 128;
    float* out = (float*)d_out;

    float *qkv_p, *o_p, *w2_p, *cw0_p, *b2_p;
    cudaGetSymbolAddress((void**)&qkv_p, g_qkv);
    cudaGetSymbolAddress((void**)&o_p,   g_o);
    cudaGetSymbolAddress((void**)&w2_p,  g_w2);
    cudaGetSymbolAddress((void**)&cw0_p, g_cw0);
    cudaGetSymbolAddress((void**)&b2_p,  g_b2);

    detect_kernel<<<1, 32>>>((const int*)nbr);
    prep_kernel<<<128, 128>>>(cw, opw, opb, cb);

    dim3 gq((N + 127) / 128, 3);
    sgemm_kernel<1><<<gq, 256>>>(x, ipw, x, ipw, ipb, qkv_p, N, 384);

    attn_kernel<<<(N + 7) / 8, 256>>>(nbr, N);

    dim3 go((N + 127) / 128, 1);
    sgemm_kernel<2><<<go, 256>>>(x, cw0_p, o_p, w2_p, b2_p, out, N, 128);
}

// round 6
// speedup vs baseline: 1.3226x; 1.3226x over previous
#include <cuda_runtime.h>
#include <cuda_bf16.h>
#include <math.h>
#include <stdint.h>

// ---------------------------------------------------------------------------
// SpatialAttentionConv, R5: family-safe bf16 mma.sync (HMMA) split-GEMMs.
// tcgen05 is rejected by this harness (PTX target sm_103, not sm_103a), so
// tensor work goes through mma.sync.m16n8k16.row.col.f32.bf16.bf16.f32.
//
//   GEMM1: D(N x 512) = X(N x 128) @ Wbig^T, Wbig = [ipw(384x128); cw0(128x128)]
//          cols 0..383 -> g_qkv (+ipb), cols 384..511 -> g_c0
//   attn : per-face 8-neighbor masked softmax, fp32 (DRAM-gather bound)
//   GEMM2: out = c0 + O @ W2^T + b2,  W2 = Cw1@Wo, b2 = Cw1@bo + cb
// Split trick: A = Ah + Al (bf16), W = Wh + Wl (bf16);
//   A@W ~= Ah@Wh + Al@Wh + Ah@Wl  (fp32 accum, ~1e-6 rel precision)
// ---------------------------------------------------------------------------

#define MAXN 200064

static __device__ float g_qkv[(size_t)MAXN * 384];
static __device__ float g_o[(size_t)MAXN * 128];
static __device__ float g_c0[(size_t)MAXN * 128];
static __device__ float g_w2[128 * 128];
static __device__ float g_b2[128];
static __device__ uint4 g_bfm[8 * 64 * 32];   // GEMM1 B frags: [ks][ntile][lane]
static __device__ uint4 g_bf2[8 * 16 * 32];   // GEMM2 B frags
static __device__ int g_is64;

// ------------------------------ helpers ------------------------------------
__device__ __forceinline__ uint32_t smem_u32(const void* p) {
    uint32_t a;
    asm("{ .reg .u64 t; cvta.to.shared.u64 t, %1; cvt.u32.u64 %0, t; }" : "=r"(a) : "l"(p));
    return a;
}
__device__ __forceinline__ uint32_t pk2(float a, float b) {
    __nv_bfloat162 t = __floats2bfloat162_rn(a, b);
    return *reinterpret_cast<uint32_t*>(&t);
}
__device__ __forceinline__ float bfl(float v) {   // v - bf16_round(v)
    return v - __bfloat162float(__float2bfloat16(v));
}

#define LDMATRIX_X4(r0, r1, r2, r3, addr) \
    asm volatile("ldmatrix.sync.aligned.m8n8.x4.shared.b16 {%0,%1,%2,%3}, [%4];" \
                 : "=r"(r0), "=r"(r1), "=r"(r2), "=r"(r3) : "r"(addr))

#define MMA16816(d, a, b0, b1) \
    asm volatile("mma.sync.aligned.m16n8k16.row.col.f32.bf16.bf16.f32 " \
                 "{%0,%1,%2,%3}, {%4,%5,%6,%7}, {%8,%9}, {%0,%1,%2,%3};" \
                 : "+f"((d)[0]), "+f"((d)[1]), "+f"((d)[2]), "+f"((d)[3]) \
                 : "r"((a)[0]), "r"((a)[1]), "r"((a)[2]), "r"((a)[3]), \
                   "r"(b0), "r"(b1))

// ------------------------------ small preps --------------------------------
__global__ void detect_kernel(const int* __restrict__ nbr32) {
    if (threadIdx.x == 0) {
        int any = 0;
        #pragma unroll 1
        for (int j = 1; j < 128; ++j) any |= nbr32[2 * j + 1];
        g_is64 = (any == 0) ? 1 : 0;
    }
}

__global__ void prep_w2_kernel(const float* __restrict__ conv_w,
                               const float* __restrict__ out_proj_w,
                               const float* __restrict__ out_proj_b,
                               const float* __restrict__ conv_b) {
    int n = blockIdx.x, i = threadIdx.x;
    float s = 0.f;
    #pragma unroll 4
    for (int m = 0; m < 128; ++m)
        s += conv_w[(n * 128 + m) * 2 + 1] * out_proj_w[m * 128 + i];
    g_w2[n * 128 + i] = s;
    if (i == 0) {
        float b = 0.f;
        for (int m = 0; m < 128; ++m)
            b += conv_w[(n * 128 + m) * 2 + 1] * out_proj_b[m];
        g_b2[n] = b + conv_b[n];
    }
}

// B fragments in mma register layout. For m16n8k16.row.col, lane l holds:
//   reg0: B[k=(l%4)*2 + {0,1},     n=l/4]
//   reg1: B[k=(l%4)*2 + 8 + {0,1}, n=l/4]
// uint4 = {bh_reg0, bh_reg1, bl_reg0, bl_reg1}.
__global__ void prep_frag_mega(const float* __restrict__ ipw,
                               const float* __restrict__ cw) {
    int idx = blockIdx.x * blockDim.x + threadIdx.x;     // 16384
    int lane = idx & 31, t = (idx >> 5) & 63, ks = idx >> 11;
    int n = t * 8 + (lane >> 2);
    int k0 = ks * 16 + (lane & 3) * 2;
    float v[4];
    #pragma unroll
    for (int j = 0; j < 4; ++j) {
        int k = k0 + (j >> 1) * 8 + (j & 1);
        v[j] = (n < 384) ? ipw[n * 128 + k] : cw[((n - 384) * 128 + k) * 2];
    }
    uint4 o;
    o.x = pk2(v[0], v[1]);
    o.y = pk2(v[2], v[3]);
    o.z = pk2(bfl(v[0]), bfl(v[1]));
    o.w = pk2(bfl(v[2]), bfl(v[3]));
    g_bfm[idx] = o;
}

__global__ void prep_frag_w2() {
    int idx = blockIdx.x * blockDim.x + threadIdx.x;     // 4096
    int lane = idx & 31, t = (idx >> 5) & 15, ks = idx >> 9;
    int n = t * 8 + (lane >> 2);
    int k0 = ks * 16 + (lane & 3) * 2;
    float v[4];
    #pragma unroll
    for (int j = 0; j < 4; ++j)
        v[j] = g_w2[n * 128 + k0 + (j >> 1) * 8 + (j & 1)];
    uint4 o;
    o.x = pk2(v[0], v[1]);
    o.y = pk2(v[2], v[3]);
    o.z = pk2(bfl(v[0]), bfl(v[1]));
    o.w = pk2(bfl(v[2]), bfl(v[3]));
    g_bf2[idx] = o;
}

// ---------------------------------------------------------------------------
// Shared A tile: 128 rows x 128 bf16 (256B/row), hi at 0, lo at 32KB.
// 16B chunk (r, c) stored at r*256 + (c ^ (r & 7))*16  -> conflict-free
// ldmatrix (8 rows of one chunk column hit 8 distinct chunks).
// ---------------------------------------------------------------------------
__device__ __forceinline__ void fill_tile(const float* __restrict__ src,
                                          char* smem, int m0, int M, int tid) {
    #pragma unroll 1
    for (int i = tid; i < 2048; i += 256) {
        int r = i >> 4, c = i & 15;
        float4 v0 = make_float4(0.f, 0.f, 0.f, 0.f), v1 = v0;
        if (m0 + r < M) {
            const float* p = src + (size_t)(m0 + r) * 128 + c * 8;
            v0 = *(const float4*)p;
            v1 = *(const float4*)(p + 4);
        }
        uint4 hi, lo;
        hi.x = pk2(v0.x, v0.y); hi.y = pk2(v0.z, v0.w);
        hi.z = pk2(v1.x, v1.y); hi.w = pk2(v1.z, v1.w);
        lo.x = pk2(bfl(v0.x), bfl(v0.y)); lo.y = pk2(bfl(v0.z), bfl(v0.w));
        lo.z = pk2(bfl(v1.x), bfl(v1.y)); lo.w = pk2(bfl(v1.z), bfl(v1.w));
        uint32_t off = (uint32_t)(r * 256 + ((c ^ (r & 7)) << 4));
        *(uint4*)(smem + off) = hi;
        *(uint4*)(smem + 32768 + off) = lo;
    }
}

// -------------------- GEMM1: QKV + conv0 -----------------------------------
// grid (4, tiles): sec = blockIdx.x (n-fastest so 4 secs of one m-tile share
// the X tile via L2), m0 = blockIdx.y*128. CTA 128x128, 8 warps 4m x 2n,
// warp tile 32x64.
__global__ void __launch_bounds__(256, 2)
mega_gemm(const float* __restrict__ x, const float* __restrict__ ipb, int M) {
    extern __shared__ char smem[];
    const int tid = threadIdx.x;
    const int sec = blockIdx.x;
    const int m0 = blockIdx.y * 128;
    const int w = tid >> 5, lane = tid & 31;
    const int wm = w & 3, wn = w >> 2;

    fill_tile(x, smem, m0, M, tid);
    __syncthreads();

    const uint32_t sb = smem_u32(smem);
    const int lr = lane & 15, lc = lane >> 4, ls = lane & 7;
    uint32_t aoff[2];
    #pragma unroll
    for (int mf = 0; mf < 2; ++mf)
        aoff[mf] = (uint32_t)((wm * 32 + mf * 16 + lr) * 256);

    float acc[2][8][4];
    #pragma unroll
    for (int mf = 0; mf < 2; ++mf)
        #pragma unroll
        for (int nf = 0; nf < 8; ++nf)
            #pragma unroll
            for (int q = 0; q < 4; ++q) acc[mf][nf][q] = 0.f;

    const uint4* __restrict__ bfr = g_bfm;
    const int ntb = sec * 16 + wn * 8;

    #pragma unroll 1
    for (int ks = 0; ks < 8; ++ks) {
        uint32_t ch = (uint32_t)((((ks * 2 + lc) ^ ls)) << 4);
        uint32_t ah[2][4], al[2][4];
        #pragma unroll
        for (int mf = 0; mf < 2; ++mf) {
            LDMATRIX_X4(ah[mf][0], ah[mf][1], ah[mf][2], ah[mf][3],
                        sb + aoff[mf] + ch);
            LDMATRIX_X4(al[mf][0], al[mf][1], al[mf][2], al[mf][3],
                        sb + 32768 + aoff[mf] + ch);
        }
        #pragma unroll
        for (int nf = 0; nf < 8; ++nf) {
            uint4 b = __ldg(&bfr[(ks * 64 + ntb + nf) * 32 + lane]);
            #pragma unroll
            for (int mf = 0; mf < 2; ++mf) {
                MMA16816(acc[mf][nf], ah[mf], b.x, b.y);
                MMA16816(acc[mf][nf], al[mf], b.x, b.y);
                MMA16816(acc[mf][nf], ah[mf], b.z, b.w);
            }
        }
    }

    // Epilogue.
    const int qrow = lane >> 2, qcol = (lane & 3) * 2;
    #pragma unroll
    for (int mf = 0; mf < 2; ++mf) {
        int r0 = m0 + wm * 32 + mf * 16 + qrow;
        #pragma unroll
        for (int nf = 0; nf < 8; ++nf) {
            int col = wn * 64 + nf * 8 + qcol;          // 0..127 local
            float b0 = 0.f, b1 = 0.f;
            float* base;
            if (sec < 3) {
                b0 = ipb[sec * 128 + col];
                b1 = ipb[sec * 128 + col + 1];
                base = g_qkv + sec * 128 + col;
                if (r0 < M)
                    *(float2*)(base + (size_t)r0 * 384) =
                        make_float2(acc[mf][nf][0] + b0, acc[mf][nf][1] + b1);
                if (r0 + 8 < M)
                    *(float2*)(base + (size_t)(r0 + 8) * 384) =
                        make_float2(acc[mf][nf][2] + b0, acc[mf][nf][3] + b1);
            } else {
                base = g_c0 + col;
                if (r0 < M)
                    *(float2*)(base + (size_t)r0 * 128) =
                        make_float2(acc[mf][nf][0], acc[mf][nf][1]);
                if (r0 + 8 < M)
                    *(float2*)(base + (size_t)(r0 + 8) * 128) =
                        make_float2(acc[mf][nf][2], acc[mf][nf][3]);
            }
        }
    }
}

// -------------------- GEMM2: out = c0 + O@W2^T + b2 ------------------------
__global__ void __launch_bounds__(256, 2)
out_gemm(float* __restrict__ out, int M) {
    extern __shared__ char smem[];
    const int tid = threadIdx.x;
    const int m0 = blockIdx.x * 128;
    const int w = tid >> 5, lane = tid & 31;
    const int wm = w & 3, wn = w >> 2;

    fill_tile(g_o, smem, m0, M, tid);
    __syncthreads();

    const uint32_t sb = smem_u32(smem);
    const int lr = lane & 15, lc = lane >> 4, ls = lane & 7;
    uint32_t aoff[2];
    #pragma unroll
    for (int mf = 0; mf < 2; ++mf)
        aoff[mf] = (uint32_t)((wm * 32 + mf * 16 + lr) * 256);

    float acc[2][8][4];
    #pragma unroll
    for (int mf = 0; mf < 2; ++mf)
        #pragma unroll
        for (int nf = 0; nf < 8; ++nf)
            #pragma unroll
            for (int q = 0; q < 4; ++q) acc[mf][nf][q] = 0.f;

    const uint4* __restrict__ bfr = g_bf2;
    const int ntb = wn * 8;

    #pragma unroll 1
    for (int ks = 0; ks < 8; ++ks) {
        uint32_t ch = (uint32_t)((((ks * 2 + lc) ^ ls)) << 4);
        uint32_t ah[2][4], al[2][4];
        #pragma unroll
        for (int mf = 0; mf < 2; ++mf) {
            LDMATRIX_X4(ah[mf][0], ah[mf][1], ah[mf][2], ah[mf][3],
                        sb + aoff[mf] + ch);
            LDMATRIX_X4(al[mf][0], al[mf][1], al[mf][2], al[mf][3],
                        sb + 32768 + aoff[mf] + ch);
        }
        #pragma unroll
        for (int nf = 0; nf < 8; ++nf) {
            uint4 b = __ldg(&bfr[(ks * 16 + ntb + nf) * 32 + lane]);
            #pragma unroll
            for (int mf = 0; mf < 2; ++mf) {
                MMA16816(acc[mf][nf], ah[mf], b.x, b.y);
                MMA16816(acc[mf][nf], al[mf], b.x, b.y);
                MMA16816(acc[mf][nf], ah[mf], b.z, b.w);
            }
        }
    }

    const int qrow = lane >> 2, qcol = (lane & 3) * 2;
    #pragma unroll
    for (int mf = 0; mf < 2; ++mf) {
        int r0 = m0 + wm * 32 + mf * 16 + qrow;
        #pragma unroll
        for (int nf = 0; nf < 8; ++nf) {
            int col = wn * 64 + nf * 8 + qcol;
            float b0 = g_b2[col], b1 = g_b2[col + 1];
            #pragma unroll
            for (int h = 0; h < 2; ++h) {
                int r = r0 + h * 8;
                if (r < M) {
                    float2 c = *(const float2*)(g_c0 + (size_t)r * 128 + col);
                    *(float2*)(out + (size_t)r * 128 + col) =
                        make_float2(acc[mf][nf][2 * h] + c.x + b0,
                                    acc[mf][nf][2 * h + 1] + c.y + b1);
                }
            }
        }
    }
}

// ------------------------------ attention ----------------------------------
__global__ void __launch_bounds__(256)
attn_kernel(const void* __restrict__ nbr, int N) {
    const int lane = threadIdx.x & 31;
    const int face = blockIdx.x * (blockDim.x >> 5) + (threadIdx.x >> 5);
    if (face >= N) return;

    const float* __restrict__ qkv = g_qkv;
    const float4 q = *(const float4*)&qkv[(size_t)face * 384 + lane * 4];

    int myj = 0;
    if (lane < 8) {
        if (g_is64) myj = (int)((const long long*)nbr)[(size_t)face * 9 + 1 + lane];
        else        myj = ((const int*)nbr)[(size_t)face * 9 + 1 + lane];
    }

    float  sc[8];
    float4 vv[8];
    const float scale = 0.17677669529663687f;  // 1/sqrt(32)

    #pragma unroll
    for (int kk = 0; kk < 8; ++kk) {
        int j = __shfl_sync(0xffffffffu, myj, kk);
        float s;
        float4 v;
        if (j < N) {
            const float* base = &qkv[(size_t)j * 384 + 128 + lane * 4];
            float4 kf = *(const float4*)base;
            v = *(const float4*)(base + 128);
            float p = q.x * kf.x + q.y * kf.y + q.z * kf.z + q.w * kf.w;
            p += __shfl_xor_sync(0xffffffffu, p, 1);
            p += __shfl_xor_sync(0xffffffffu, p, 2);
            p += __shfl_xor_sync(0xffffffffu, p, 4);
            s = p * scale;
        } else {
            s = -INFINITY;
            v = make_float4(0.f, 0.f, 0.f, 0.f);
        }
        sc[kk] = s;
        vv[kk] = v;
    }

    float m = sc[0];
    #pragma unroll
    for (int kk = 1; kk < 8; ++kk) m = fmaxf(m, sc[kk]);
    float den = 0.f;
    #pragma unroll
    for (int kk = 0; kk < 8; ++kk) { float e = __expf(sc[kk] - m); sc[kk] = e; den += e; }
    const float inv = 1.0f / den;

    float4 acc = make_float4(0.f, 0.f, 0.f, 0.f);
    #pragma unroll
    for (int kk = 0; kk < 8; ++kk) {
        acc.x += sc[kk] * vv[kk].x;
        acc.y += sc[kk] * vv[kk].y;
        acc.z += sc[kk] * vv[kk].z;
        acc.w += sc[kk] * vv[kk].w;
    }
    acc.x *= inv; acc.y *= inv; acc.z *= inv; acc.w *= inv;

    *(float4*)&g_o[(size_t)face * 128 + lane * 4] = acc;
}

// ------------------------------ launch -------------------------------------
extern "C" void kernel_launch(void* const* d_in, const int* in_sizes, int n_in,
                              void* d_out, int out_size) {
    const float* x   = (const float*)d_in[0];
    const void*  nbr = d_in[1];
    const float* ipw = (const float*)d_in[4];
    const float* ipb = (const float*)d_in[5];
    const float* opw = (const float*)d_in[6];
    const float* opb = (const float*)d_in[7];
    const float* cw  = (const float*)d_in[8];
    const float* cb  = (const float*)d_in[9];
    const int N = in_sizes[0] / 128;
    float* out = (float*)d_out;

    const int SMEM = 65536;
    cudaFuncSetAttribute(mega_gemm, cudaFuncAttributeMaxDynamicSharedMemorySize, SMEM);
    cudaFuncSetAttribute(out_gemm, cudaFuncAttributeMaxDynamicSharedMemorySize, SMEM);

    const int tiles = (N + 127) / 128;

    detect_kernel<<<1, 32>>>((const int*)nbr);
    prep_w2_kernel<<<128, 128>>>(cw, opw, opb, cb);
    prep_frag_mega<<<64, 256>>>(ipw, cw);
    prep_frag_w2<<<16, 256>>>();

    dim3 g1(4, tiles);
    mega_gemm<<<g1, 256, SMEM>>>(x, ipb, N);
    attn_kernel<<<(N + 7) / 8, 256>>>(nbr, N);
    out_gemm<<<tiles, 256, SMEM>>>(out, N);
}

// round 8
// speedup vs baseline: 1.3952x; 1.0549x over previous
#include <cuda_runtime.h>
#include <cuda_bf16.h>
#include <math.h>
#include <stdint.h>

// ---------------------------------------------------------------------------
// SpatialAttentionConv, R7 (re-bench; prior attempt was an infra failure):
// bf16 HMMA split-GEMMs with SMEM-staged coalesced epilogues; conv-tap0
// folded into GEMM2 (no g_c0 roundtrip).
//
//   GEMM1: g_qkv(N x 384) = X @ ipw^T + ipb          (3 n-sections)
//   attn : per-face 8-neighbor masked softmax, fp32
//   GEMM2: out = X @ cw0^T + O @ W2^T + b2,  W2 = Cw1@Wo, b2 = Cw1@bo + cb
// Split trick: A = Ah + Al (bf16); A@W ~= Ah@Wh + Al@Wh + Ah@Wl (fp32 accum).
// ---------------------------------------------------------------------------

#define MAXN 200064

static __device__ float g_qkv[(size_t)MAXN * 384];
static __device__ float g_o[(size_t)MAXN * 128];
static __device__ float g_w2[128 * 128];
static __device__ float g_b2[128];
static __device__ uint4 g_bfm[8 * 64 * 32];   // B frags: [ks][ntile 0..63][lane]
                                              // ntile 0..47: ipw, 48..63: cw0
static __device__ uint4 g_bf2[8 * 16 * 32];   // W2 frags
static __device__ int g_is64;

// ------------------------------ helpers ------------------------------------
__device__ __forceinline__ uint32_t smem_u32(const void* p) {
    uint32_t a;
    asm("{ .reg .u64 t; cvta.to.shared.u64 t, %1; cvt.u32.u64 %0, t; }" : "=r"(a) : "l"(p));
    return a;
}
__device__ __forceinline__ uint32_t pk2(float a, float b) {
    __nv_bfloat162 t = __floats2bfloat162_rn(a, b);
    return *reinterpret_cast<uint32_t*>(&t);
}
__device__ __forceinline__ float bfl(float v) {   // v - bf16_round(v)
    return v - __bfloat162float(__float2bfloat16(v));
}

#define LDMATRIX_X4(r0, r1, r2, r3, addr) \
    asm volatile("ldmatrix.sync.aligned.m8n8.x4.shared.b16 {%0,%1,%2,%3}, [%4];" \
                 : "=r"(r0), "=r"(r1), "=r"(r2), "=r"(r3) : "r"(addr))

#define MMA16816(d, a, b0, b1) \
    asm volatile("mma.sync.aligned.m16n8k16.row.col.f32.bf16.bf16.f32 " \
                 "{%0,%1,%2,%3}, {%4,%5,%6,%7}, {%8,%9}, {%0,%1,%2,%3};" \
                 : "+f"((d)[0]), "+f"((d)[1]), "+f"((d)[2]), "+f"((d)[3]) \
                 : "r"((a)[0]), "r"((a)[1]), "r"((a)[2]), "r"((a)[3]), \
                   "r"(b0), "r"(b1))

#define ST_STRIDE 132               // staging row stride in floats (bank spread)
#define SMEM_BYTES (128 * ST_STRIDE * 4)   // 67584 >= 65536 tile bytes

// ------------------------------ small preps --------------------------------
__global__ void detect_kernel(const int* __restrict__ nbr32) {
    if (threadIdx.x == 0) {
        int any = 0;
        #pragma unroll 1
        for (int j = 1; j < 128; ++j) any |= nbr32[2 * j + 1];
        g_is64 = (any == 0) ? 1 : 0;
    }
}

__global__ void prep_w2_kernel(const float* __restrict__ conv_w,
                               const float* __restrict__ out_proj_w,
                               const float* __restrict__ out_proj_b,
                               const float* __restrict__ conv_b) {
    int n = blockIdx.x, i = threadIdx.x;
    float s = 0.f;
    #pragma unroll 4
    for (int m = 0; m < 128; ++m)
        s += conv_w[(n * 128 + m) * 2 + 1] * out_proj_w[m * 128 + i];
    g_w2[n * 128 + i] = s;
    if (i == 0) {
        float b = 0.f;
        for (int m = 0; m < 128; ++m)
            b += conv_w[(n * 128 + m) * 2 + 1] * out_proj_b[m];
        g_b2[n] = b + conv_b[n];
    }
}

// B fragments in mma register layout (m16n8k16.row.col):
//   reg0: B[k=(l%4)*2+{0,1},   n=l/4];  reg1: B[k=(l%4)*2+8+{0,1}, n=l/4]
// uint4 = {bh_reg0, bh_reg1, bl_reg0, bl_reg1}.
__global__ void prep_frag_mega(const float* __restrict__ ipw,
                               const float* __restrict__ cw) {
    int idx = blockIdx.x * blockDim.x + threadIdx.x;     // 16384
    int lane = idx & 31, t = (idx >> 5) & 63, ks = idx >> 11;
    int n = t * 8 + (lane >> 2);
    int k0 = ks * 16 + (lane & 3) * 2;
    float v[4];
    #pragma unroll
    for (int j = 0; j < 4; ++j) {
        int k = k0 + (j >> 1) * 8 + (j & 1);
        v[j] = (n < 384) ? ipw[n * 128 + k] : cw[((n - 384) * 128 + k) * 2];
    }
    uint4 o;
    o.x = pk2(v[0], v[1]);
    o.y = pk2(v[2], v[3]);
    o.z = pk2(bfl(v[0]), bfl(v[1]));
    o.w = pk2(bfl(v[2]), bfl(v[3]));
    g_bfm[idx] = o;
}

__global__ void prep_frag_w2() {
    int idx = blockIdx.x * blockDim.x + threadIdx.x;     // 4096
    int lane = idx & 31, t = (idx >> 5) & 15, ks = idx >> 9;
    int n = t * 8 + (lane >> 2);
    int k0 = ks * 16 + (lane & 3) * 2;
    float v[4];
    #pragma unroll
    for (int j = 0; j < 4; ++j)
        v[j] = g_w2[n * 128 + k0 + (j >> 1) * 8 + (j & 1)];
    uint4 o;
    o.x = pk2(v[0], v[1]);
    o.y = pk2(v[2], v[3]);
    o.z = pk2(bfl(v[0]), bfl(v[1]));
    o.w = pk2(bfl(v[2]), bfl(v[3]));
    g_bf2[idx] = o;
}

// ---------------------------------------------------------------------------
// Shared A tile: 128 rows x 128 bf16 (256B/row), hi at 0, lo at 32KB.
// 16B chunk (r, c) at r*256 + (c ^ (r & 7))*16 -> conflict-free ldmatrix.
// ---------------------------------------------------------------------------
__device__ __forceinline__ void fill_tile(const float* __restrict__ src,
                                          char* smem, int m0, int M, int tid) {
    #pragma unroll 1
    for (int i = tid; i < 2048; i += 256) {
        int r = i >> 4, c = i & 15;
        float4 v0 = make_float4(0.f, 0.f, 0.f, 0.f), v1 = v0;
        if (m0 + r < M) {
            const float* p = src + (size_t)(m0 + r) * 128 + c * 8;
            v0 = *(const float4*)p;
            v1 = *(const float4*)(p + 4);
        }
        uint4 hi, lo;
        hi.x = pk2(v0.x, v0.y); hi.y = pk2(v0.z, v0.w);
        hi.z = pk2(v1.x, v1.y); hi.w = pk2(v1.z, v1.w);
        lo.x = pk2(bfl(v0.x), bfl(v0.y)); lo.y = pk2(bfl(v0.z), bfl(v0.w));
        lo.z = pk2(bfl(v1.x), bfl(v1.y)); lo.w = pk2(bfl(v1.z), bfl(v1.w));
        uint32_t off = (uint32_t)(r * 256 + ((c ^ (r & 7)) << 4));
        *(uint4*)(smem + off) = hi;
        *(uint4*)(smem + 32768 + off) = lo;
    }
}

// MMA pass over the SMEM A tile vs one 128-col B fragment block.
__device__ __forceinline__ void mma_pass(uint32_t sb, const uint4* __restrict__ bfr,
                                         int ntb, int nstride, int lane,
                                         int wm, float acc[2][8][4]) {
    const int lr = lane & 15, lc = lane >> 4, ls = lane & 7;
    uint32_t aoff[2];
    #pragma unroll
    for (int mf = 0; mf < 2; ++mf)
        aoff[mf] = (uint32_t)((wm * 32 + mf * 16 + lr) * 256);

    #pragma unroll 1
    for (int ks = 0; ks < 8; ++ks) {
        uint32_t ch = (uint32_t)((((ks * 2 + lc) ^ ls)) << 4);
        uint32_t ah[2][4], al[2][4];
        #pragma unroll
        for (int mf = 0; mf < 2; ++mf) {
            LDMATRIX_X4(ah[mf][0], ah[mf][1], ah[mf][2], ah[mf][3],
                        sb + aoff[mf] + ch);
            LDMATRIX_X4(al[mf][0], al[mf][1], al[mf][2], al[mf][3],
                        sb + 32768 + aoff[mf] + ch);
        }
        #pragma unroll
        for (int nf = 0; nf < 8; ++nf) {
            uint4 b = __ldg(&bfr[(ks * nstride + ntb + nf) * 32 + lane]);
            #pragma unroll
            for (int mf = 0; mf < 2; ++mf) {
                MMA16816(acc[mf][nf], ah[mf], b.x, b.y);
                MMA16816(acc[mf][nf], al[mf], b.x, b.y);
                MMA16816(acc[mf][nf], ah[mf], b.z, b.w);
            }
        }
    }
}

// Stage accumulators to padded SMEM (local 128x128 tile).
__device__ __forceinline__ void stage_acc(float* st, int wm, int wn, int lane,
                                          float acc[2][8][4]) {
    const int qrow = lane >> 2, qcol = (lane & 3) * 2;
    #pragma unroll
    for (int mf = 0; mf < 2; ++mf) {
        int r = wm * 32 + mf * 16 + qrow;
        #pragma unroll
        for (int nf = 0; nf < 8; ++nf) {
            int c = wn * 64 + nf * 8 + qcol;
            st[r * ST_STRIDE + c]           = acc[mf][nf][0];
            st[r * ST_STRIDE + c + 1]       = acc[mf][nf][1];
            st[(r + 8) * ST_STRIDE + c]     = acc[mf][nf][2];
            st[(r + 8) * ST_STRIDE + c + 1] = acc[mf][nf][3];
        }
    }
}

// -------------------- GEMM1: QKV (3 sections of 128) -----------------------
// grid (3, tiles): sec n-fastest so the 3 secs of one m-tile share X via L2.
__global__ void __launch_bounds__(256, 2)
mega_gemm(const float* __restrict__ x, const float* __restrict__ ipb, int M) {
    extern __shared__ char smem[];
    const int tid = threadIdx.x;
    const int sec = blockIdx.x;
    const int m0 = blockIdx.y * 128;
    const int w = tid >> 5, lane = tid & 31;
    const int wm = w & 3, wn = w >> 2;

    fill_tile(x, smem, m0, M, tid);
    __syncthreads();

    float acc[2][8][4];
    #pragma unroll
    for (int mf = 0; mf < 2; ++mf)
        #pragma unroll
        for (int nf = 0; nf < 8; ++nf)
            #pragma unroll
            for (int q = 0; q < 4; ++q) acc[mf][nf][q] = 0.f;

    mma_pass(smem_u32(smem), g_bfm, sec * 16 + wn * 8, 64, lane, wm, acc);

    // Staged, coalesced epilogue.
    __syncthreads();                      // all warps done reading A tile
    float* st = (float*)smem;
    stage_acc(st, wm, wn, lane, acc);
    __syncthreads();

    #pragma unroll 1
    for (int i = tid; i < 4096; i += 256) {
        int r = i >> 5, c = (i & 31) << 2;
        if (m0 + r < M) {
            float4 v = *(const float4*)&st[r * ST_STRIDE + c];
            float4 b = *(const float4*)(ipb + sec * 128 + c);
            v.x += b.x; v.y += b.y; v.z += b.z; v.w += b.w;
            *(float4*)(g_qkv + (size_t)(m0 + r) * 384 + sec * 128 + c) = v;
        }
    }
}

// -------------------- GEMM2: out = X@cw0^T + O@W2^T + b2 -------------------
__global__ void __launch_bounds__(256, 2)
out_gemm(const float* __restrict__ x, float* __restrict__ out, int M) {
    extern __shared__ char smem[];
    const int tid = threadIdx.x;
    const int m0 = blockIdx.x * 128;
    const int w = tid >> 5, lane = tid & 31;
    const int wm = w & 3, wn = w >> 2;

    float acc[2][8][4];
    #pragma unroll
    for (int mf = 0; mf < 2; ++mf)
        #pragma unroll
        for (int nf = 0; nf < 8; ++nf)
            #pragma unroll
            for (int q = 0; q < 4; ++q) acc[mf][nf][q] = 0.f;

    // Pass 1: O @ W2^T
    fill_tile(g_o, smem, m0, M, tid);
    __syncthreads();
    mma_pass(smem_u32(smem), g_bf2, wn * 8, 16, lane, wm, acc);
    __syncthreads();

    // Pass 2: X @ cw0^T (cw0 = ntiles 48..63 of g_bfm)
    fill_tile(x, smem, m0, M, tid);
    __syncthreads();
    mma_pass(smem_u32(smem), g_bfm, 48 + wn * 8, 64, lane, wm, acc);

    // Staged, coalesced epilogue.
    __syncthreads();
    float* st = (float*)smem;
    stage_acc(st, wm, wn, lane, acc);
    __syncthreads();

    #pragma unroll 1
    for (int i = tid; i < 4096; i += 256) {
        int r = i >> 5, c = (i & 31) << 2;
        if (m0 + r < M) {
            float4 v = *(const float4*)&st[r * ST_STRIDE + c];
            float4 b = *(const float4*)(g_b2 + c);
            v.x += b.x; v.y += b.y; v.z += b.z; v.w += b.w;
            *(float4*)(out + (size_t)(m0 + r) * 128 + c) = v;
        }
    }
}

// ------------------------------ attention ----------------------------------
__global__ void __launch_bounds__(256)
attn_kernel(const void* __restrict__ nbr, int N) {
    const int lane = threadIdx.x & 31;
    const int face = blockIdx.x * (blockDim.x >> 5) + (threadIdx.x >> 5);
    if (face >= N) return;

    const float* __restrict__ qkv = g_qkv;
    const float4 q = *(const float4*)&qkv[(size_t)face * 384 + lane * 4];

    int myj = 0;
    if (lane < 8) {
        if (g_is64) myj = (int)((const long long*)nbr)[(size_t)face * 9 + 1 + lane];
        else        myj = ((const int*)nbr)[(size_t)face * 9 + 1 + lane];
    }

    float  sc[8];
    float4 vv[8];
    const float scale = 0.17677669529663687f;  // 1/sqrt(32)

    #pragma unroll
    for (int kk = 0; kk < 8; ++kk) {
        int j = __shfl_sync(0xffffffffu, myj, kk);
        float s;
        float4 v;
        if (j < N) {
            const float* base = &qkv[(size_t)j * 384 + 128 + lane * 4];
            float4 kf = *(const float4*)base;
            v = *(const float4*)(base + 128);
            float p = q.x * kf.x + q.y * kf.y + q.z * kf.z + q.w * kf.w;
            p += __shfl_xor_sync(0xffffffffu, p, 1);
            p += __shfl_xor_sync(0xffffffffu, p, 2);
            p += __shfl_xor_sync(0xffffffffu, p, 4);
            s = p * scale;
        } else {
            s = -INFINITY;
            v = make_float4(0.f, 0.f, 0.f, 0.f);
        }
        sc[kk] = s;
        vv[kk] = v;
    }

    float m = sc[0];
    #pragma unroll
    for (int kk = 1; kk < 8; ++kk) m = fmaxf(m, sc[kk]);
    float den = 0.f;
    #pragma unroll
    for (int kk = 0; kk < 8; ++kk) { float e = __expf(sc[kk] - m); sc[kk] = e; den += e; }
    const float inv = 1.0f / den;

    float4 acc = make_float4(0.f, 0.f, 0.f, 0.f);
    #pragma unroll
    for (int kk = 0; kk < 8; ++kk) {
        acc.x += sc[kk] * vv[kk].x;
        acc.y += sc[kk] * vv[kk].y;
        acc.z += sc[kk] * vv[kk].z;
        acc.w += sc[kk] * vv[kk].w;
    }
    acc.x *= inv; acc.y *= inv; acc.z *= inv; acc.w *= inv;

    *(float4*)&g_o[(size_t)face * 128 + lane * 4] = acc;
}

// ------------------------------ launch -------------------------------------
extern "C" void kernel_launch(void* const* d_in, const int* in_sizes, int n_in,
                              void* d_out, int out_size) {
    const float* x   = (const float*)d_in[0];
    const void*  nbr = d_in[1];
    const float* ipw = (const float*)d_in[4];
    const float* ipb = (const float*)d_in[5];
    const float* opw = (const float*)d_in[6];
    const float* opb = (const float*)d_in[7];
    const float* cw  = (const float*)d_in[8];
    const float* cb  = (const float*)d_in[9];
    const int N = in_sizes[0] / 128;
    float* out = (float*)d_out;

    cudaFuncSetAttribute(mega_gemm, cudaFuncAttributeMaxDynamicSharedMemorySize, SMEM_BYTES);
    cudaFuncSetAttribute(out_gemm, cudaFuncAttributeMaxDynamicSharedMemorySize, SMEM_BYTES);

    const int tiles = (N + 127) / 128;

    detect_kernel<<<1, 32>>>((const int*)nbr);
    prep_w2_kernel<<<128, 128>>>(cw, opw, opb, cb);
    prep_frag_mega<<<64, 256>>>(ipw, cw);
    prep_frag_w2<<<16, 256>>>();

    dim3 g1(3, tiles);
    mega_gemm<<<g1, 256, SMEM_BYTES>>>(x, ipb, N);
    attn_kernel<<<(N + 7) / 8, 256>>>(nbr, N);
    out_gemm<<<tiles, 256, SMEM_BYTES>>>(x, out, N);
}